// round 2
// baseline (speedup 1.0000x reference)
#include <cuda_runtime.h>
#include <cstdint>

#define DD 32
#define HH 64
#define NB 4096
#define EPSF 1e-10f

// Scratch (allocation-free rule: __device__ globals)
__device__ float g_V[(size_t)NB * DD * HH];   // [r][i][h]  33.5 MB
__device__ float g_CA[NB * HH];               // [r][h]
__device__ int   g_off[NB + 1];

typedef unsigned long long u64;

__device__ __forceinline__ u64 fma2(u64 a, u64 b, u64 c) {
    u64 d; asm("fma.rn.f32x2 %0, %1, %2, %3;" : "=l"(d) : "l"(a), "l"(b), "l"(c)); return d;
}
__device__ __forceinline__ u64 add2(u64 a, u64 b) {
    u64 d; asm("add.rn.f32x2 %0, %1, %2;" : "=l"(d) : "l"(a), "l"(b)); return d;
}
__device__ __forceinline__ u64 pack2(float lo, float hi) {
    u64 d; asm("mov.b64 %0, {%1, %2};" : "=l"(d) : "f"(lo), "f"(hi)); return d;
}
__device__ __forceinline__ void unpack2(u64 a, float& lo, float& hi) {
    asm("mov.b64 {%0, %1}, %2;" : "=f"(lo), "=f"(hi) : "l"(a));
}

// ---------------------------------------------------------------------------
// Kernel C: segment offsets from sorted row_ids.  g_off[q] = lower_bound(row_ids, q)
// ---------------------------------------------------------------------------
__global__ void build_offsets(const int* __restrict__ row_ids, int T) {
    int t = blockIdx.x * blockDim.x + threadIdx.x;
    if (t >= T) return;
    int r  = row_ids[t];
    int rp = (t == 0) ? -1 : row_ids[t - 1];
    for (int q = rp + 1; q <= r; q++) g_off[q] = t;
    if (t == T - 1) {
        for (int q = r + 1; q <= NB; q++) g_off[q] = T;
    }
}

// ---------------------------------------------------------------------------
// Kernel A: per-candidate precompute.
//   grid (128 r-tiles, 17), 128 threads.
//   nt<16 : V[r,i,h] = W1[(32+i),h] + sum_j c[r,j] * W1[64+i*32+j, h]
//   nt==16: CA[r,h]  = b1[h] + sum_j c[r,j] * W1[j, h]
// ---------------------------------------------------------------------------
__global__ void __launch_bounds__(128) precompute_V(
    const float* __restrict__ cand,
    const float* __restrict__ W1,
    const float* __restrict__ b1)
{
    __shared__ __align__(16) float cs[32 * 32];   // c tile [32 r][32 j]
    int rt  = blockIdx.x;
    int nt  = blockIdx.y;
    int tid = threadIdx.x;

    // candidate rows are contiguous: flat copy 1024 floats
    const float4* csrc = (const float4*)(cand + (size_t)rt * 32 * DD);
    float4* cdst = (float4*)cs;
    cdst[tid]       = csrc[tid];
    cdst[tid + 128] = csrc[tid + 128];
    __syncthreads();

    if (nt < 16) {
        int n = nt * 128 + tid;          // n = i*64 + h
        int i = n >> 6, h = n & 63;
        const float* wbase = W1 + (size_t)(64 + i * 32) * HH + h;   // + j*HH per j

        u64 acc2[32];
        #pragma unroll
        for (int rr = 0; rr < 32; rr++) acc2[rr] = 0ull;

        #pragma unroll
        for (int j4 = 0; j4 < 8; j4++) {
            float w0 = wbase[(j4 * 4 + 0) * HH];
            float w1v = wbase[(j4 * 4 + 1) * HH];
            float w2v = wbase[(j4 * 4 + 2) * HH];
            float w3v = wbase[(j4 * 4 + 3) * HH];
            u64 bp0 = pack2(w0, w1v);
            u64 bp1 = pack2(w2v, w3v);
            #pragma unroll
            for (int rr = 0; rr < 32; rr++) {
                ulonglong2 cc = *(const ulonglong2*)&cs[rr * 32 + j4 * 4];
                acc2[rr] = fma2(cc.x, bp0, acc2[rr]);
                acc2[rr] = fma2(cc.y, bp1, acc2[rr]);
            }
        }
        float wb = W1[(size_t)(32 + i) * HH + h];
        float* dst = g_V + (size_t)(rt * 32) * (DD * HH) + n;
        #pragma unroll
        for (int rr = 0; rr < 32; rr++) {
            float lo, hi; unpack2(acc2[rr], lo, hi);
            dst[(size_t)rr * (DD * HH)] = wb + lo + hi;
        }
    } else if (tid < 64) {
        int h = tid;
        float accs[32];
        float bb = b1[h];
        #pragma unroll
        for (int rr = 0; rr < 32; rr++) accs[rr] = bb;
        #pragma unroll 4
        for (int j = 0; j < 32; j++) {
            float wv = W1[(size_t)j * HH + h];
            #pragma unroll
            for (int rr = 0; rr < 32; rr++)
                accs[rr] = fmaf(cs[rr * 32 + j], wv, accs[rr]);
        }
        float* dst = g_CA + rt * 32 * HH + h;
        #pragma unroll
        for (int rr = 0; rr < 32; rr++) dst[rr * HH] = accs[rr];
    }
}

// ---------------------------------------------------------------------------
// Kernel B: main fused kernel. One block (64 thr, 2 warps) per candidate r.
// lane = row; per-lane full dice; register segment-sum; no atomics.
// ---------------------------------------------------------------------------
__global__ void __launch_bounds__(64, 6) attn_main(
    const float* __restrict__ behavior,
    const float* __restrict__ alpha,
    const float* __restrict__ W2,
    const float* __restrict__ b2,
    float* __restrict__ out)
{
    __shared__ __align__(16) float Vs[DD * HH];   // 8 KB
    __shared__ __align__(16) float cas[HH];
    __shared__ __align__(16) float als[HH];
    __shared__ __align__(16) float w2s[HH];
    __shared__ float partial[2][DD];

    int r    = blockIdx.x;
    int tid  = threadIdx.x;
    int lane = tid & 31;
    int wid  = tid >> 5;

    {
        const float4* src = (const float4*)(g_V + (size_t)r * (DD * HH));
        float4* dst = (float4*)Vs;
        #pragma unroll
        for (int k = 0; k < 8; k++) dst[k * 64 + tid] = src[k * 64 + tid];
        cas[tid] = g_CA[r * HH + tid];
        als[tid] = alpha[tid];
        w2s[tid] = W2[tid];
    }
    float b2v  = b2[0];
    int start  = g_off[r];
    int end    = g_off[r + 1];
    __syncthreads();

    float acc[DD];
    #pragma unroll
    for (int d = 0; d < DD; d++) acc[d] = 0.f;

    for (int base = start + wid * 32; base < end; base += 64) {
        int t = base + lane;
        bool active = (t < end);

        float b[DD];
        if (active) {
            const float4* brow = (const float4*)(behavior + (size_t)t * DD);
            #pragma unroll
            for (int k = 0; k < 8; k++) {
                float4 v = brow[k];
                b[4*k+0] = v.x; b[4*k+1] = v.y; b[4*k+2] = v.z; b[4*k+3] = v.w;
            }
        } else {
            #pragma unroll
            for (int k = 0; k < DD; k++) b[k] = 0.f;
        }

        // x[64] = CA[r] + b . V[r]   (packed f32x2, 2 h per reg-pair)
        u64 x2[HH / 2];
        {
            const ulonglong2* cp = (const ulonglong2*)cas;
            #pragma unroll
            for (int pp = 0; pp < 16; pp++) {
                ulonglong2 v = cp[pp];
                x2[2*pp] = v.x; x2[2*pp+1] = v.y;
            }
        }
        #pragma unroll
        for (int i = 0; i < DD; i++) {
            u64 bb = pack2(b[i], b[i]);
            const ulonglong2* vp = (const ulonglong2*)&Vs[i * HH];
            #pragma unroll
            for (int pp = 0; pp < 16; pp++) {
                ulonglong2 v = vp[pp];
                x2[2*pp]   = fma2(v.x, bb, x2[2*pp]);
                x2[2*pp+1] = fma2(v.y, bb, x2[2*pp+1]);
            }
        }

        // dice: mean
        u64 sa = x2[0], sb = x2[1], sc = x2[2], sd = x2[3];
        #pragma unroll
        for (int p = 4; p < 32; p += 4) {
            sa = add2(sa, x2[p]);   sb = add2(sb, x2[p+1]);
            sc = add2(sc, x2[p+2]); sd = add2(sd, x2[p+3]);
        }
        u64 st = add2(add2(sa, sb), add2(sc, sd));
        float slo, shi; unpack2(st, slo, shi);
        float mean = (slo + shi) * (1.0f / 64.0f);

        // variance (EPS added inside the mean per reference: mean(sq)+EPS)
        u64 nm = pack2(-mean, -mean);
        u64 va = 0ull, vb = 0ull, vc = 0ull, vd = 0ull;
        #pragma unroll
        for (int p = 0; p < 32; p += 4) {
            u64 d0 = add2(x2[p],   nm); va = fma2(d0, d0, va);
            u64 d1 = add2(x2[p+1], nm); vb = fma2(d1, d1, vb);
            u64 d2 = add2(x2[p+2], nm); vc = fma2(d2, d2, vc);
            u64 d3 = add2(x2[p+3], nm); vd = fma2(d3, d3, vd);
        }
        u64 vt = add2(add2(va, vb), add2(vc, vd));
        float vlo, vhi; unpack2(vt, vlo, vhi);
        float var  = (vlo + vhi) * (1.0f / 64.0f) + EPSF;
        float stdv = sqrtf(var);
        float rinv = __fdividef(1.0f, stdv + EPSF);
        float nri  = -rinv;
        float mri  = mean * rinv;   // exp(-(x-mean)*rinv) = exp(fma(x, nri, mri))

        float w = b2v;
        #pragma unroll
        for (int pp = 0; pp < 16; pp++) {
            float4 al4 = *(const float4*)&als[pp * 4];
            float4 w24 = *(const float4*)&w2s[pp * 4];
            float xa, xb, xc, xd;
            unpack2(x2[2*pp],   xa, xb);
            unpack2(x2[2*pp+1], xc, xd);
            {
                float e = __expf(fmaf(xa, nri, mri));
                float p = __fdividef(1.0f, 1.0f + e);
                float cf = fmaf(p, 1.0f - al4.x, al4.x);
                w = fmaf(xa * cf, w24.x, w);
            }
            {
                float e = __expf(fmaf(xb, nri, mri));
                float p = __fdividef(1.0f, 1.0f + e);
                float cf = fmaf(p, 1.0f - al4.y, al4.y);
                w = fmaf(xb * cf, w24.y, w);
            }
            {
                float e = __expf(fmaf(xc, nri, mri));
                float p = __fdividef(1.0f, 1.0f + e);
                float cf = fmaf(p, 1.0f - al4.z, al4.z);
                w = fmaf(xc * cf, w24.z, w);
            }
            {
                float e = __expf(fmaf(xd, nri, mri));
                float p = __fdividef(1.0f, 1.0f + e);
                float cf = fmaf(p, 1.0f - al4.w, al4.w);
                w = fmaf(xd * cf, w24.w, w);
            }
        }
        if (!active) w = 0.0f;   // b==0 anyway; belt & braces
        #pragma unroll
        for (int d = 0; d < DD; d++) acc[d] = fmaf(b[d], w, acc[d]);
    }

    // cross-lane reduce (once per block): after butterfly all lanes hold totals
    #pragma unroll
    for (int d = 0; d < DD; d++) {
        #pragma unroll
        for (int s = 16; s > 0; s >>= 1)
            acc[d] += __shfl_xor_sync(0xffffffffu, acc[d], s);
    }
    partial[wid][lane] = acc[lane];
    __syncthreads();
    if (wid == 0)
        out[(size_t)r * DD + lane] = partial[0][lane] + partial[1][lane];
}

// ---------------------------------------------------------------------------
extern "C" void kernel_launch(void* const* d_in, const int* in_sizes, int n_in,
                              void* d_out, int out_size) {
    const float* cand    = (const float*)d_in[0];
    const float* behav   = (const float*)d_in[1];
    const int*   row_ids = (const int*)  d_in[2];
    const float* W1      = (const float*)d_in[3];
    const float* b1      = (const float*)d_in[4];
    const float* alphaP  = (const float*)d_in[5];
    const float* W2      = (const float*)d_in[6];
    const float* b2      = (const float*)d_in[7];
    float* out = (float*)d_out;
    int T = in_sizes[2];

    build_offsets<<<(T + 255) / 256, 256>>>(row_ids, T);
    precompute_V<<<dim3(128, 17), 128>>>(cand, W1, b1);
    attn_main<<<NB, 64>>>(behav, alphaP, W2, b2, out);
}

// round 3
// speedup vs baseline: 1.4430x; 1.4430x over previous
#include <cuda_runtime.h>
#include <cstdint>

#define DD 32
#define HH 64
#define NB 4096
#define EPSF 1e-10f
#define BSTRIDE 33   // padded row stride (floats) for behavior tile: conflict-free both ways

// Scratch (allocation-free rule: __device__ globals)
__device__ float g_V[(size_t)NB * DD * HH];   // [r][i][h]  33.5 MB
__device__ float g_CA[NB * HH];               // [r][h]

typedef unsigned long long u64;

__device__ __forceinline__ u64 fma2(u64 a, u64 b, u64 c) {
    u64 d; asm("fma.rn.f32x2 %0, %1, %2, %3;" : "=l"(d) : "l"(a), "l"(b), "l"(c)); return d;
}
__device__ __forceinline__ u64 add2(u64 a, u64 b) {
    u64 d; asm("add.rn.f32x2 %0, %1, %2;" : "=l"(d) : "l"(a), "l"(b)); return d;
}
__device__ __forceinline__ u64 pack2(float lo, float hi) {
    u64 d; asm("mov.b64 %0, {%1, %2};" : "=l"(d) : "f"(lo), "f"(hi)); return d;
}
__device__ __forceinline__ void unpack2(u64 a, float& lo, float& hi) {
    asm("mov.b64 {%0, %1}, %2;" : "=f"(lo), "=f"(hi) : "l"(a));
}

// ---------------------------------------------------------------------------
// Kernel A: per-candidate precompute.
//   grid (128 r-tiles, 17), 128 threads.
//   nt<16 : V[r,i,h] = W1[(32+i),h] + sum_j c[r,j] * W1[64+i*32+j, h]
//   nt==16: CA[r,h]  = b1[h] + sum_j c[r,j] * W1[j, h]
// ---------------------------------------------------------------------------
__global__ void __launch_bounds__(128) precompute_V(
    const float* __restrict__ cand,
    const float* __restrict__ W1,
    const float* __restrict__ b1)
{
    __shared__ __align__(16) float cs[32 * 32];   // c tile [32 r][32 j]
    int rt  = blockIdx.x;
    int nt  = blockIdx.y;
    int tid = threadIdx.x;

    const float4* csrc = (const float4*)(cand + (size_t)rt * 32 * DD);
    float4* cdst = (float4*)cs;
    cdst[tid]       = csrc[tid];
    cdst[tid + 128] = csrc[tid + 128];
    __syncthreads();

    if (nt < 16) {
        int n = nt * 128 + tid;          // n = i*64 + h
        int i = n >> 6, h = n & 63;
        const float* wbase = W1 + (size_t)(64 + i * 32) * HH + h;

        u64 acc2[32];
        #pragma unroll
        for (int rr = 0; rr < 32; rr++) acc2[rr] = 0ull;

        #pragma unroll
        for (int j4 = 0; j4 < 8; j4++) {
            float w0  = wbase[(j4 * 4 + 0) * HH];
            float w1v = wbase[(j4 * 4 + 1) * HH];
            float w2v = wbase[(j4 * 4 + 2) * HH];
            float w3v = wbase[(j4 * 4 + 3) * HH];
            u64 bp0 = pack2(w0, w1v);
            u64 bp1 = pack2(w2v, w3v);
            #pragma unroll
            for (int rr = 0; rr < 32; rr++) {
                ulonglong2 cc = *(const ulonglong2*)&cs[rr * 32 + j4 * 4];
                acc2[rr] = fma2(cc.x, bp0, acc2[rr]);
                acc2[rr] = fma2(cc.y, bp1, acc2[rr]);
            }
        }
        float wb = W1[(size_t)(32 + i) * HH + h];
        float* dst = g_V + (size_t)(rt * 32) * (DD * HH) + n;
        #pragma unroll
        for (int rr = 0; rr < 32; rr++) {
            float lo, hi; unpack2(acc2[rr], lo, hi);
            dst[(size_t)rr * (DD * HH)] = wb + lo + hi;
        }
    } else if (tid < 64) {
        int h = tid;
        float accs[32];
        float bb = b1[h];
        #pragma unroll
        for (int rr = 0; rr < 32; rr++) accs[rr] = bb;
        #pragma unroll 4
        for (int j = 0; j < 32; j++) {
            float wv = W1[(size_t)j * HH + h];
            #pragma unroll
            for (int rr = 0; rr < 32; rr++)
                accs[rr] = fmaf(cs[rr * 32 + j], wv, accs[rr]);
        }
        float* dst = g_CA + rt * 32 * HH + h;
        #pragma unroll
        for (int rr = 0; rr < 32; rr++) dst[rr * HH] = accs[rr];
    }
}

// ---------------------------------------------------------------------------
// Kernel B: main fused kernel. One block (64 thr, 2 warps) per candidate r.
// Behavior tile staged in smem (stride-33) -> no per-lane b[] / acc[] arrays,
// no register spills. Per-block binary search replaces the offsets kernel.
// ---------------------------------------------------------------------------
__global__ void __launch_bounds__(64, 8) attn_main(
    const float* __restrict__ behavior,
    const int*   __restrict__ row_ids,
    int T,
    const float* __restrict__ alpha,
    const float* __restrict__ W2,
    const float* __restrict__ b2,
    float* __restrict__ out)
{
    __shared__ __align__(16) float Vs[DD * HH];     // 8 KB
    __shared__ float bs[64 * BSTRIDE];              // 8.25 KB behavior tile
    __shared__ __align__(16) float cas[HH];
    __shared__ __align__(16) float als[HH];
    __shared__ __align__(16) float w2s[HH];
    __shared__ float partial[2][DD];
    __shared__ int   seg[2];

    int r    = blockIdx.x;
    int tid  = threadIdx.x;
    int lane = tid & 31;
    int wid  = tid >> 5;

    // stage V[r], CA[r], params
    {
        const float4* src = (const float4*)(g_V + (size_t)r * (DD * HH));
        float4* dst = (float4*)Vs;
        #pragma unroll
        for (int k = 0; k < 8; k++) dst[k * 64 + tid] = src[k * 64 + tid];
        cas[tid] = g_CA[r * HH + tid];
        als[tid] = alpha[tid];
        w2s[tid] = W2[tid];
    }
    // per-block segment bounds: lower_bound(row_ids, r) / lower_bound(row_ids, r+1)
    if (tid < 2) {
        int target = r + tid;
        int lo = 0, hi = T;
        while (lo < hi) {
            int mid = (lo + hi) >> 1;
            if (row_ids[mid] < target) lo = mid + 1; else hi = mid;
        }
        seg[tid] = lo;
    }
    float b2v = b2[0];
    __syncthreads();

    int start = seg[0];
    int end   = seg[1];

    float accd = 0.f;   // lane owns output dim d = lane (per warp)

    for (int base = start; base < end; base += 64) {
        int nrows = end - base; if (nrows > 64) nrows = 64;

        // cooperative coalesced load of up to 64 rows into bs (stride 33)
        {
            const float4* gsrc = (const float4*)(behavior + (size_t)base * DD);
            int n4 = nrows * 8;                       // float4 count
            for (int idx = tid; idx < n4; idx += 64) {
                float4 v = gsrc[idx];
                int row = idx >> 3, col = (idx & 7) << 2;
                float* d = &bs[row * BSTRIDE + col];
                d[0] = v.x; d[1] = v.y; d[2] = v.z; d[3] = v.w;
            }
        }
        __syncthreads();

        // ---- matvec: x[64] = CA + b_row . V ----
        const float* brow = &bs[(wid * 32 + lane) * BSTRIDE];
        u64 x2[HH / 2];
        {
            const ulonglong2* cp = (const ulonglong2*)cas;
            #pragma unroll
            for (int pp = 0; pp < 16; pp++) {
                ulonglong2 v = cp[pp];
                x2[2*pp] = v.x; x2[2*pp+1] = v.y;
            }
        }
        #pragma unroll
        for (int i = 0; i < DD; i++) {
            float bi = brow[i];                       // conflict-free: (lane*33+i)%32 distinct
            u64 bb = pack2(bi, bi);
            const ulonglong2* vp = (const ulonglong2*)&Vs[i * HH];
            #pragma unroll
            for (int pp = 0; pp < 16; pp++) {
                ulonglong2 v = vp[pp];
                x2[2*pp]   = fma2(v.x, bb, x2[2*pp]);
                x2[2*pp+1] = fma2(v.y, bb, x2[2*pp+1]);
            }
        }

        // ---- dice: mean ----
        u64 sa = x2[0], sb = x2[1], sc = x2[2], sd = x2[3];
        #pragma unroll
        for (int p = 4; p < 32; p += 4) {
            sa = add2(sa, x2[p]);   sb = add2(sb, x2[p+1]);
            sc = add2(sc, x2[p+2]); sd = add2(sd, x2[p+3]);
        }
        u64 st = add2(add2(sa, sb), add2(sc, sd));
        float slo, shi; unpack2(st, slo, shi);
        float mean = (slo + shi) * (1.0f / 64.0f);

        // ---- variance ----
        u64 nm = pack2(-mean, -mean);
        u64 va = 0ull, vb = 0ull, vc = 0ull, vd = 0ull;
        #pragma unroll
        for (int p = 0; p < 32; p += 4) {
            u64 d0 = add2(x2[p],   nm); va = fma2(d0, d0, va);
            u64 d1 = add2(x2[p+1], nm); vb = fma2(d1, d1, vb);
            u64 d2 = add2(x2[p+2], nm); vc = fma2(d2, d2, vc);
            u64 d3 = add2(x2[p+3], nm); vd = fma2(d3, d3, vd);
        }
        u64 vt = add2(add2(va, vb), add2(vc, vd));
        float vlo, vhi; unpack2(vt, vlo, vhi);
        float var  = (vlo + vhi) * (1.0f / 64.0f) + EPSF;
        float stdv = sqrtf(var);
        float rinv = __fdividef(1.0f, stdv + EPSF);
        float nri  = -rinv;
        float mri  = mean * rinv;   // exp(-(x-mean)*rinv) = exp(fma(x, nri, mri))

        // ---- dice activation + W2 dot ----
        float w = b2v;
        #pragma unroll
        for (int pp = 0; pp < 16; pp++) {
            float4 al4 = *(const float4*)&als[pp * 4];
            float4 w24 = *(const float4*)&w2s[pp * 4];
            float xa, xb, xc, xd;
            unpack2(x2[2*pp],   xa, xb);
            unpack2(x2[2*pp+1], xc, xd);
            { float e = __expf(fmaf(xa, nri, mri)); float p = __fdividef(1.f, 1.f + e);
              w = fmaf(xa * fmaf(p, 1.f - al4.x, al4.x), w24.x, w); }
            { float e = __expf(fmaf(xb, nri, mri)); float p = __fdividef(1.f, 1.f + e);
              w = fmaf(xb * fmaf(p, 1.f - al4.y, al4.y), w24.y, w); }
            { float e = __expf(fmaf(xc, nri, mri)); float p = __fdividef(1.f, 1.f + e);
              w = fmaf(xc * fmaf(p, 1.f - al4.z, al4.z), w24.z, w); }
            { float e = __expf(fmaf(xd, nri, mri)); float p = __fdividef(1.f, 1.f + e);
              w = fmaf(xd * fmaf(p, 1.f - al4.w, al4.w), w24.w, w); }
        }

        // ---- warp segment-sum epilogue: lane owns dim d = lane ----
        int nvalid = nrows - wid * 32;
        if (nvalid > 32) nvalid = 32;
        for (int rr = 0; rr < nvalid; rr++) {
            float wr = __shfl_sync(0xffffffffu, w, rr);
            accd = fmaf(bs[(wid * 32 + rr) * BSTRIDE + lane], wr, accd);
        }
        __syncthreads();   // bs reused next iteration
    }

    partial[wid][lane] = accd;
    __syncthreads();
    if (wid == 0)
        out[(size_t)r * DD + lane] = partial[0][lane] + partial[1][lane];
}

// ---------------------------------------------------------------------------
extern "C" void kernel_launch(void* const* d_in, const int* in_sizes, int n_in,
                              void* d_out, int out_size) {
    const float* cand    = (const float*)d_in[0];
    const float* behav   = (const float*)d_in[1];
    const int*   row_ids = (const int*)  d_in[2];
    const float* W1      = (const float*)d_in[3];
    const float* b1      = (const float*)d_in[4];
    const float* alphaP  = (const float*)d_in[5];
    const float* W2      = (const float*)d_in[6];
    const float* b2      = (const float*)d_in[7];
    float* out = (float*)d_out;
    int T = in_sizes[2];

    precompute_V<<<dim3(128, 17), 128>>>(cand, W1, b1);
    attn_main<<<NB, 64>>>(behav, row_ids, T, alphaP, W2, b2, out);
}